// round 15
// baseline (speedup 1.0000x reference)
#include <cuda_runtime.h>
#include <cuda_bf16.h>
#include <cstdint>

#define MSA 256
#define SEQ 384
#define DM  256
#define DH  32
#define DP  128
#define EPSV 1e-5f

#define AROWS 12288          // SEQ*DH rows for GEMM1 operands
#define PAIRS (SEQ*SEQ)      // 147456

#define BK   64              // K-chunk
#define SPAD 72              // smem row pitch in bf16 (64 data + 8 pad)
#define NK1  12              // gemm1 K' chunks (768/64)
#define NKE  48              // epilogue-gemm K' chunks (3072/64)

#define ABYTES (128 * SPAD * 2)          // one operand, one stage (18432 B)
#define STAGEB (2 * ABYTES)              // A+B one stage (36864 B)

// epilogue smem layout
#define A2PITCH 2056                     // bf16 pitch for A2 (2048 + 8 pad)
#define A2BYTES (16 * A2PITCH * 2)       // 65792 B
#define WO_OFF  A2BYTES                  // wo double-buffer after A2
#define WOSTAGE (128 * SPAD * 2)         // 18432 B per stage
#define SMEMSZ  (WO_OFF + 2 * WOSTAGE)   // 102656 B (>= 2*STAGEB for mainloop)

// ---------------- scratch (device globals; no allocations allowed) ----------
__device__ __nv_bfloat16 g_l[AROWS * 512];
__device__ __nv_bfloat16 g_r[AROWS * 512];
__device__ __nv_bfloat16 g_wo[DP * 2048];
__device__ float g_count[SEQ * SEQ];

// ---------------- helpers ---------------------------------------------------
__device__ __forceinline__ uint32_t smem_u32(const void* p) {
    uint32_t a;
    asm("{ .reg .u64 t; cvta.to.shared.u64 t, %1; cvt.u32.u64 %0, t; }"
        : "=r"(a) : "l"(p));
    return a;
}
__device__ __forceinline__ uint32_t pack_bf16(__nv_bfloat16 a, __nv_bfloat16 b) {
    return (uint32_t)__bfloat16_as_ushort(a) | ((uint32_t)__bfloat16_as_ushort(b) << 16);
}
__device__ __forceinline__ void ldmat_x4(uint32_t* r, uint32_t addr) {
    asm volatile("ldmatrix.sync.aligned.m8n8.x4.shared.b16 {%0,%1,%2,%3}, [%4];"
                 : "=r"(r[0]), "=r"(r[1]), "=r"(r[2]), "=r"(r[3]) : "r"(addr));
}
__device__ __forceinline__ void mma16816(float* c, const uint32_t* a,
                                         uint32_t b0, uint32_t b1) {
    asm volatile(
        "mma.sync.aligned.m16n8k16.row.col.f32.bf16.bf16.f32 "
        "{%0,%1,%2,%3}, {%4,%5,%6,%7}, {%8,%9}, {%0,%1,%2,%3};"
        : "+f"(c[0]), "+f"(c[1]), "+f"(c[2]), "+f"(c[3])
        : "r"(a[0]), "r"(a[1]), "r"(a[2]), "r"(a[3]), "r"(b0), "r"(b1));
}
__device__ __forceinline__ void cp16(uint32_t dst, const void* src) {
    asm volatile("cp.async.ca.shared.global [%0], [%1], 16;" :: "r"(dst), "l"(src));
}
__device__ __forceinline__ void cp_commit() {
    asm volatile("cp.async.commit_group;" ::: "memory");
}
__device__ __forceinline__ void cp_wait1() {
    asm volatile("cp.async.wait_group 1;" ::: "memory");
}
__device__ __forceinline__ void cp_wait0() {
    asm volatile("cp.async.wait_group 0;" ::: "memory");
}

// ---------------------------------------------------------------------------
// Kernel 1: LayerNorm + projections; writes L'/R' as bf16 hi/lo split in
// GEMM1 operand layout (row = i*32+c, col = m (hi) / 256+m (lo)).
// Block = 64 threads: one i, 32 consecutive m. mask is int32.
// ---------------------------------------------------------------------------
__global__ void ln_proj_kernel(const float* __restrict__ x,
                               const int* __restrict__ mask,
                               const float* __restrict__ ln_g,
                               const float* __restrict__ ln_b,
                               const float* __restrict__ wl,
                               const float* __restrict__ bl,
                               const float* __restrict__ wr,
                               const float* __restrict__ br)
{
    __shared__ float xns[32][DM];

    const int t = threadIdx.x;          // 0..63
    const int r = t >> 3;               // 0..7
    const int lane8 = t & 7;
    const int i  = blockIdx.x >> 3;
    const int m0 = (blockIdx.x & 7) * 32;

    const float4* g4 = (const float4*)ln_g;
    const float4* b4 = (const float4*)ln_b;

#pragma unroll
    for (int it = 0; it < 4; it++) {
        const int rr = it * 8 + r;
        const size_t rowg = (size_t)(m0 + rr) * SEQ + i;
        const float4* xrow = (const float4*)(x + rowg * DM);

        float4 v[8];
        float s = 0.f, ss = 0.f;
#pragma unroll
        for (int kk = 0; kk < 8; kk++) {
            v[kk] = xrow[kk * 8 + lane8];
            s  += v[kk].x + v[kk].y + v[kk].z + v[kk].w;
            ss += v[kk].x * v[kk].x + v[kk].y * v[kk].y
                + v[kk].z * v[kk].z + v[kk].w * v[kk].w;
        }
#pragma unroll
        for (int off = 4; off >= 1; off >>= 1) {
            s  += __shfl_xor_sync(0xffffffffu, s,  off);
            ss += __shfl_xor_sync(0xffffffffu, ss, off);
        }
        const float mu   = s * (1.0f / DM);
        const float var  = ss * (1.0f / DM) - mu * mu;
        const float rstd = rsqrtf(var + EPSV);

#pragma unroll
        for (int kk = 0; kk < 8; kk++) {
            float4 gg = g4[kk * 8 + lane8];
            float4 bb = b4[kk * 8 + lane8];
            float4 o;
            o.x = (v[kk].x - mu) * rstd * gg.x + bb.x;
            o.y = (v[kk].y - mu) * rstd * gg.y + bb.y;
            o.z = (v[kk].z - mu) * rstd * gg.z + bb.z;
            o.w = (v[kk].w - mu) * rstd * gg.w + bb.w;
            ((float4*)&xns[rr][0])[kk * 8 + lane8] = o;
        }
    }
    __syncthreads();

    const float* W  = (t < DH) ? wl : wr;
    const float* Bv = (t < DH) ? bl : br;
    const int c = t & 31;

    float acc[32];
#pragma unroll
    for (int rr = 0; rr < 32; rr++) acc[rr] = 0.f;

    for (int kc = 0; kc < DM; kc += 8) {
        float wreg[8];
#pragma unroll
        for (int kk = 0; kk < 8; kk++)
            wreg[kk] = W[(kc + kk) * DH + c];
#pragma unroll
        for (int rr = 0; rr < 32; rr++) {
            float a = acc[rr];
#pragma unroll
            for (int kk = 0; kk < 8; kk++)
                a += xns[rr][kc + kk] * wreg[kk];
            acc[rr] = a;
        }
    }

    const float bias = Bv[c];
#pragma unroll
    for (int rr = 0; rr < 32; rr++) {
        const float mf = (mask[(m0 + rr) * SEQ + i] != 0) ? 1.0f : 0.0f;
        acc[rr] = (acc[rr] + bias) * mf;
    }

    __nv_bfloat16* dst = ((t < DH) ? g_l : g_r) + ((size_t)(i * 32 + c)) * 512;
#pragma unroll
    for (int q = 0; q < 4; q++) {
        uint32_t hw[4], lw[4];
#pragma unroll
        for (int u = 0; u < 4; u++) {
            const float v0 = acc[q * 8 + u * 2];
            const float v1 = acc[q * 8 + u * 2 + 1];
            __nv_bfloat16 h0 = __float2bfloat16(v0);
            __nv_bfloat16 h1 = __float2bfloat16(v1);
            __nv_bfloat16 l0 = __float2bfloat16(v0 - __bfloat162float(h0));
            __nv_bfloat16 l1 = __float2bfloat16(v1 - __bfloat162float(h1));
            hw[u] = pack_bf16(h0, h1);
            lw[u] = pack_bf16(l0, l1);
        }
        *(uint4*)(dst + m0 + q * 8)       = make_uint4(hw[0], hw[1], hw[2], hw[3]);
        *(uint4*)(dst + 256 + m0 + q * 8) = make_uint4(lw[0], lw[1], lw[2], lw[3]);
    }
}

// ---------------------------------------------------------------------------
// Kernel 2: pairwise mask count (int32 mask)
// ---------------------------------------------------------------------------
__global__ void count_kernel(const int* __restrict__ mask)
{
    const int i = blockIdx.x;
    const int j0 = threadIdx.x;
    float acc0 = 0.f, acc1 = 0.f, acc2 = 0.f;
    for (int m = 0; m < MSA; m++) {
        const int* mrow = mask + m * SEQ;
        const float mi = (mrow[i] != 0) ? 1.0f : 0.0f;
        acc0 += mi * ((mrow[j0]       != 0) ? 1.0f : 0.0f);
        acc1 += mi * ((mrow[j0 + 128] != 0) ? 1.0f : 0.0f);
        acc2 += mi * ((mrow[j0 + 256] != 0) ? 1.0f : 0.0f);
    }
    g_count[i * SEQ + j0]       = acc0;
    g_count[i * SEQ + j0 + 128] = acc1;
    g_count[i * SEQ + j0 + 256] = acc2;
}

// ---------------------------------------------------------------------------
// Kernel 3: transpose+split wo -> g_wo[p][cd hi | cd lo]
// ---------------------------------------------------------------------------
__global__ void wo_prep_kernel(const float* __restrict__ wo)
{
    const int p = blockIdx.x;
    for (int k = threadIdx.x; k < 1024; k += 256) {
        float v = wo[(size_t)k * DP + p];
        __nv_bfloat16 h = __float2bfloat16(v);
        __nv_bfloat16 l = __float2bfloat16(v - __bfloat162float(h));
        g_wo[(size_t)p * 2048 + k]        = h;
        g_wo[(size_t)p * 2048 + 1024 + k] = l;
    }
}

// ---------------------------------------------------------------------------
// FUSED GEMM: outer tile (128x128, K'=768) then in-CTA projection by wo
// (M=16 pairs, N=128, K'=3072) + bias + count-normalize. No g_outer.
// CTA 128 threads, 4 warps (2x2 in mainloop; N-split in epilogue).
// ---------------------------------------------------------------------------
__global__ void __launch_bounds__(128, 2)
fused_kernel(const float* __restrict__ bo, float* __restrict__ out)
{
    extern __shared__ __align__(16) char dsm[];
    const uint32_t s0 = smem_u32(dsm);

    const int tid  = threadIdx.x;
    const int wid  = tid >> 5;
    const int lane = tid & 31;
    const int warpM = wid & 1;
    const int warpN = wid >> 1;
    const int aRow0 = blockIdx.x * 128;
    const int bRow0 = blockIdx.y * 128;
    const int lj = tid & 7;             // col group for loads
    const int lr = tid >> 3;            // 0..15

    const uint32_t aFragOff =
        (uint32_t)(((warpM * 64 + (lane & 15)) * SPAD + ((lane >> 4) << 3)) * 2);
    const uint32_t bFragOff =
        (uint32_t)(((warpN * 64 + (lane & 7) + ((lane >> 4) << 3)) * SPAD
                    + (((lane >> 3) & 1) << 3)) * 2);

    float acc[4][8][4];
#pragma unroll
    for (int mt = 0; mt < 4; mt++)
#pragma unroll
        for (int nt = 0; nt < 8; nt++)
#pragma unroll
            for (int e = 0; e < 4; e++) acc[mt][nt][e] = 0.f;

    // ======================= mainloop (R13 structure) =======================
    auto issue = [&](int kc) {
        const int st = kc & 1;
        const int k0 = kc * BK;
        const int colA = (k0 < 256) ? k0 : k0 - 256;
        const int colB = (k0 < 512) ? k0 : k0 - 512;
        const uint32_t sa = s0 + st * STAGEB;
        const uint32_t sb = sa + ABYTES;
#pragma unroll
        for (int q = 0; q < 8; q++) {
            const int r = lr + q * 16;
            cp16(sa + (uint32_t)((r * SPAD + lj * 8) * 2),
                 &g_l[(size_t)(aRow0 + r) * 512 + colA + lj * 8]);
            cp16(sb + (uint32_t)((r * SPAD + lj * 8) * 2),
                 &g_r[(size_t)(bRow0 + r) * 512 + colB + lj * 8]);
        }
        cp_commit();
    };

    uint32_t af[2][4][4], bf_[2][4][4];

    issue(0);
    for (int kc = 0; kc < NK1; kc++) {
        if (kc + 1 < NK1) { issue(kc + 1); cp_wait1(); }
        else              { cp_wait0(); }
        __syncthreads();
        const int st = kc & 1;
        const uint32_t sa = s0 + st * STAGEB;
        const uint32_t sb = sa + ABYTES;

#pragma unroll
        for (int mt = 0; mt < 4; mt++)
            ldmat_x4(af[0][mt], sa + aFragOff + mt * (16 * SPAD * 2));
#pragma unroll
        for (int g = 0; g < 4; g++)
            ldmat_x4(bf_[0][g], sb + bFragOff + g * (16 * SPAD * 2));

#pragma unroll
        for (int ks = 0; ks < 4; ks++) {
            const int cur = ks & 1;
            if (ks < 3) {
                const uint32_t ko = (uint32_t)((ks + 1) * 32);
#pragma unroll
                for (int mt = 0; mt < 4; mt++)
                    ldmat_x4(af[cur ^ 1][mt], sa + aFragOff + mt * (16 * SPAD * 2) + ko);
#pragma unroll
                for (int g = 0; g < 4; g++)
                    ldmat_x4(bf_[cur ^ 1][g], sb + bFragOff + g * (16 * SPAD * 2) + ko);
            }
#pragma unroll
            for (int nt = 0; nt < 8; nt++) {
                const uint32_t b0 = bf_[cur][nt >> 1][(nt & 1) * 2];
                const uint32_t b1 = bf_[cur][nt >> 1][(nt & 1) * 2 + 1];
#pragma unroll
                for (int mt = 0; mt < 4; mt++)
                    mma16816(acc[mt][nt], af[cur][mt], b0, b1);
            }
        }
        __syncthreads();
    }

    // ================ stage acc -> A2[16 pairs][2048 hi|lo] =================
    __nv_bfloat16* A2 = (__nv_bfloat16*)dsm;
#pragma unroll
    for (int mt = 0; mt < 4; mt++)
#pragma unroll
        for (int nt = 0; nt < 8; nt++)
#pragma unroll
            for (int h = 0; h < 2; h++) {
                const int rA = warpM * 64 + mt * 16 + (lane >> 2) + h * 8;
                const int cB = warpN * 64 + nt * 8 + (lane & 3) * 2;
                const int ii = rA >> 5, c = rA & 31;
                const int jj = cB >> 5, d = cB & 31;
                const int lp = ii * 4 + jj;
                const int cd = c * 32 + d;
                const float v0 = acc[mt][nt][h * 2 + 0];
                const float v1 = acc[mt][nt][h * 2 + 1];
                __nv_bfloat16 h0 = __float2bfloat16(v0);
                __nv_bfloat16 h1 = __float2bfloat16(v1);
                __nv_bfloat16 l0 = __float2bfloat16(v0 - __bfloat162float(h0));
                __nv_bfloat16 l1 = __float2bfloat16(v1 - __bfloat162float(h1));
                *(uint32_t*)&A2[lp * A2PITCH + cd]        = pack_bf16(h0, h1);
                *(uint32_t*)&A2[lp * A2PITCH + 1024 + cd] = pack_bf16(l0, l1);
            }
    __syncthreads();

    // ============ epilogue GEMM: out16x128 = A2(16xK') x g_wo^T =============
    // warp w owns N columns [w*32, w*32+32)
    auto issue_wo = [&](int kc) {
        const int st = kc & 1;
        const int k0 = kc * BK;
        const int colB = (k0 < 2048) ? k0 : k0 - 2048;
        const uint32_t sb = s0 + WO_OFF + st * WOSTAGE;
#pragma unroll
        for (int q = 0; q < 8; q++) {
            const int r = lr + q * 16;
            cp16(sb + (uint32_t)((r * SPAD + lj * 8) * 2),
                 &g_wo[(size_t)r * 2048 + colB + lj * 8]);
        }
        cp_commit();
    };

    const uint32_t a2FragBase =
        s0 + (uint32_t)(((lane & 15) * A2PITCH + ((lane >> 4) << 3)) * 2);
    const uint32_t bFragOffE =
        (uint32_t)(((wid * 32 + (lane & 7) + ((lane >> 4) << 3)) * SPAD
                    + (((lane >> 3) & 1) << 3)) * 2);

    float acc2[4][4];
#pragma unroll
    for (int nt = 0; nt < 4; nt++)
#pragma unroll
        for (int e = 0; e < 4; e++) acc2[nt][e] = 0.f;

    issue_wo(0);
    for (int kc = 0; kc < NKE; kc++) {
        if (kc + 1 < NKE) { issue_wo(kc + 1); cp_wait1(); }
        else              { cp_wait0(); }
        __syncthreads();
        const int k0 = kc * BK;
        const uint32_t colA2 = (uint32_t)(((k0 < 1024) ? k0 : k0 - 1024) * 2);
        const uint32_t sb = s0 + WO_OFF + (kc & 1) * WOSTAGE;

#pragma unroll
        for (int ks = 0; ks < 4; ks++) {
            const uint32_t ko = (uint32_t)(ks * 32);
            uint32_t a2f[4];
            ldmat_x4(a2f, a2FragBase + colA2 + ko);
            uint32_t bfe[2][4];
#pragma unroll
            for (int g = 0; g < 2; g++)
                ldmat_x4(bfe[g], sb + bFragOffE + g * (16 * SPAD * 2) + ko);
#pragma unroll
            for (int nt = 0; nt < 4; nt++) {
                const uint32_t b0 = bfe[nt >> 1][(nt & 1) * 2];
                const uint32_t b1 = bfe[nt >> 1][(nt & 1) * 2 + 1];
                mma16816(acc2[nt], a2f, b0, b1);
            }
        }
        __syncthreads();
    }

    // ---- write out: (acc2 + bo) / (count + eps) ----
    const int i0 = blockIdx.x * 4;
    const int j0 = blockIdx.y * 4;
#pragma unroll
    for (int h = 0; h < 2; h++) {
        const int lp = (lane >> 2) + h * 8;          // local pair 0..15
        const int gi = i0 + (lp >> 2);
        const int gj = j0 + (lp & 3);
        const size_t pair = (size_t)gi * SEQ + gj;
        const float inv = 1.0f / (g_count[pair] + EPSV);
#pragma unroll
        for (int nt = 0; nt < 4; nt++) {
            const int p = wid * 32 + nt * 8 + (lane & 3) * 2;
            float2 o;
            o.x = (acc2[nt][h * 2 + 0] + bo[p])     * inv;
            o.y = (acc2[nt][h * 2 + 1] + bo[p + 1]) * inv;
            *(float2*)&out[pair * DP + p] = o;
        }
    }
}

// ---------------------------------------------------------------------------
extern "C" void kernel_launch(void* const* d_in, const int* in_sizes, int n_in,
                              void* d_out, int out_size)
{
    const float* x    = (const float*)d_in[0];
    const int*   mk   = (const int*)d_in[1];
    const float* ln_g = (const float*)d_in[2];
    const float* ln_b = (const float*)d_in[3];
    const float* wl   = (const float*)d_in[4];
    const float* bl   = (const float*)d_in[5];
    const float* wr   = (const float*)d_in[6];
    const float* br   = (const float*)d_in[7];
    const float* wo   = (const float*)d_in[8];
    const float* bo   = (const float*)d_in[9];
    float* out        = (float*)d_out;

    cudaFuncSetAttribute(fused_kernel,
                         cudaFuncAttributeMaxDynamicSharedMemorySize, SMEMSZ);

    ln_proj_kernel<<<SEQ * 8, 64>>>(x, mk, ln_g, ln_b, wl, bl, wr, br);
    count_kernel<<<SEQ, 128>>>(mk);
    wo_prep_kernel<<<DP, 256>>>(wo);
    fused_kernel<<<dim3(AROWS / 128, AROWS / 128), 128, SMEMSZ>>>(bo, out);
}

// round 16
// speedup vs baseline: 1.9823x; 1.9823x over previous
#include <cuda_runtime.h>
#include <cuda_bf16.h>
#include <cstdint>

#define MSA 256
#define SEQ 384
#define DM  256
#define DH  32
#define DP  128
#define EPSV 1e-5f

#define AROWS 12288          // SEQ*DH rows for GEMM1 operands
#define PAIRS (SEQ*SEQ)      // 147456

#define BKF   32             // K-chunk in f32 elements
#define SPADF 36             // smem row pitch in f32 (32 data + 4 pad)
#define NK1   8              // gemm1 K chunks (256/32)
#define NK2   32             // gemm2 K chunks (1024/32)

#define ABYTES (128 * SPADF * 4)         // one operand, one stage (18432 B)
#define STAGEB (2 * ABYTES)              // A+B one stage (36864 B)
#define SMEMSZ (2 * STAGEB)              // 73728 B

// ---------------- scratch (device globals; no allocations allowed) ----------
// L'/R': row = i*32+c (resp j*32+d), cols = m (256 f32, tf32-rounded)
__device__ float g_lf[AROWS * 256];
__device__ float g_rf[AROWS * 256];
// outer: row = pair (i*384+j), 1024 f32 (cd = c*32+d), tf32-rounded
__device__ float g_outer[(size_t)PAIRS * 1024];
// wo transposed: row = p, col = cd (tf32-rounded)
__device__ float g_wo[DP * 1024];
__device__ float g_count[SEQ * SEQ];

// ---------------- helpers ---------------------------------------------------
__device__ __forceinline__ uint32_t smem_u32(const void* p) {
    uint32_t a;
    asm("{ .reg .u64 t; cvta.to.shared.u64 t, %1; cvt.u32.u64 %0, t; }"
        : "=r"(a) : "l"(p));
    return a;
}
// round f32 -> tf32 (round-to-nearest), returned as f32 bit pattern
__device__ __forceinline__ float tf32r(float x) {
    uint32_t u;
    asm("cvt.rna.tf32.f32 %0, %1;" : "=r"(u) : "f"(x));
    return __uint_as_float(u);
}
__device__ __forceinline__ void ldmat_x4(uint32_t* r, uint32_t addr) {
    asm volatile("ldmatrix.sync.aligned.m8n8.x4.shared.b16 {%0,%1,%2,%3}, [%4];"
                 : "=r"(r[0]), "=r"(r[1]), "=r"(r[2]), "=r"(r[3]) : "r"(addr));
}
__device__ __forceinline__ void mma_tf32(float* c, const uint32_t* a,
                                         uint32_t b0, uint32_t b1) {
    asm volatile(
        "mma.sync.aligned.m16n8k8.row.col.f32.tf32.tf32.f32 "
        "{%0,%1,%2,%3}, {%4,%5,%6,%7}, {%8,%9}, {%0,%1,%2,%3};"
        : "+f"(c[0]), "+f"(c[1]), "+f"(c[2]), "+f"(c[3])
        : "r"(a[0]), "r"(a[1]), "r"(a[2]), "r"(a[3]), "r"(b0), "r"(b1));
}
__device__ __forceinline__ void cp16(uint32_t dst, const void* src) {
    asm volatile("cp.async.ca.shared.global [%0], [%1], 16;" :: "r"(dst), "l"(src));
}
__device__ __forceinline__ void cp_commit() {
    asm volatile("cp.async.commit_group;" ::: "memory");
}
__device__ __forceinline__ void cp_wait1() {
    asm volatile("cp.async.wait_group 1;" ::: "memory");
}
__device__ __forceinline__ void cp_wait0() {
    asm volatile("cp.async.wait_group 0;" ::: "memory");
}

// ---------------------------------------------------------------------------
// Kernel 1: LayerNorm + projections; writes L'/R' as tf32-rounded f32 in
// GEMM1 operand layout (row = i*32+c, col = m). Block = 64 threads:
// one i, 32 consecutive m. mask is int32.
// ---------------------------------------------------------------------------
__global__ void ln_proj_kernel(const float* __restrict__ x,
                               const int* __restrict__ mask,
                               const float* __restrict__ ln_g,
                               const float* __restrict__ ln_b,
                               const float* __restrict__ wl,
                               const float* __restrict__ bl,
                               const float* __restrict__ wr,
                               const float* __restrict__ br)
{
    __shared__ float xns[32][DM];

    const int t = threadIdx.x;          // 0..63
    const int r = t >> 3;               // 0..7
    const int lane8 = t & 7;
    const int i  = blockIdx.x >> 3;
    const int m0 = (blockIdx.x & 7) * 32;

    const float4* g4 = (const float4*)ln_g;
    const float4* b4 = (const float4*)ln_b;

#pragma unroll
    for (int it = 0; it < 4; it++) {
        const int rr = it * 8 + r;
        const size_t rowg = (size_t)(m0 + rr) * SEQ + i;
        const float4* xrow = (const float4*)(x + rowg * DM);

        float4 v[8];
        float s = 0.f, ss = 0.f;
#pragma unroll
        for (int kk = 0; kk < 8; kk++) {
            v[kk] = xrow[kk * 8 + lane8];
            s  += v[kk].x + v[kk].y + v[kk].z + v[kk].w;
            ss += v[kk].x * v[kk].x + v[kk].y * v[kk].y
                + v[kk].z * v[kk].z + v[kk].w * v[kk].w;
        }
#pragma unroll
        for (int off = 4; off >= 1; off >>= 1) {
            s  += __shfl_xor_sync(0xffffffffu, s,  off);
            ss += __shfl_xor_sync(0xffffffffu, ss, off);
        }
        const float mu   = s * (1.0f / DM);
        const float var  = ss * (1.0f / DM) - mu * mu;
        const float rstd = rsqrtf(var + EPSV);

#pragma unroll
        for (int kk = 0; kk < 8; kk++) {
            float4 gg = g4[kk * 8 + lane8];
            float4 bb = b4[kk * 8 + lane8];
            float4 o;
            o.x = (v[kk].x - mu) * rstd * gg.x + bb.x;
            o.y = (v[kk].y - mu) * rstd * gg.y + bb.y;
            o.z = (v[kk].z - mu) * rstd * gg.z + bb.z;
            o.w = (v[kk].w - mu) * rstd * gg.w + bb.w;
            ((float4*)&xns[rr][0])[kk * 8 + lane8] = o;
        }
    }
    __syncthreads();

    const float* W  = (t < DH) ? wl : wr;
    const float* Bv = (t < DH) ? bl : br;
    const int c = t & 31;

    float acc[32];
#pragma unroll
    for (int rr = 0; rr < 32; rr++) acc[rr] = 0.f;

    for (int kc = 0; kc < DM; kc += 8) {
        float wreg[8];
#pragma unroll
        for (int kk = 0; kk < 8; kk++)
            wreg[kk] = W[(kc + kk) * DH + c];
#pragma unroll
        for (int rr = 0; rr < 32; rr++) {
            float a = acc[rr];
#pragma unroll
            for (int kk = 0; kk < 8; kk++)
                a += xns[rr][kc + kk] * wreg[kk];
            acc[rr] = a;
        }
    }

    const float bias = Bv[c];
    float* dst = ((t < DH) ? g_lf : g_rf) + (size_t)(i * 32 + c) * 256 + m0;
#pragma unroll
    for (int q = 0; q < 8; q++) {
        float4 o;
        const float mf0 = (mask[(m0 + q * 4 + 0) * SEQ + i] != 0) ? 1.0f : 0.0f;
        const float mf1 = (mask[(m0 + q * 4 + 1) * SEQ + i] != 0) ? 1.0f : 0.0f;
        const float mf2 = (mask[(m0 + q * 4 + 2) * SEQ + i] != 0) ? 1.0f : 0.0f;
        const float mf3 = (mask[(m0 + q * 4 + 3) * SEQ + i] != 0) ? 1.0f : 0.0f;
        o.x = tf32r((acc[q * 4 + 0] + bias) * mf0);
        o.y = tf32r((acc[q * 4 + 1] + bias) * mf1);
        o.z = tf32r((acc[q * 4 + 2] + bias) * mf2);
        o.w = tf32r((acc[q * 4 + 3] + bias) * mf3);
        *(float4*)(dst + q * 4) = o;
    }
}

// ---------------------------------------------------------------------------
// Kernel 2: pairwise mask count (int32 mask)
// ---------------------------------------------------------------------------
__global__ void count_kernel(const int* __restrict__ mask)
{
    const int i = blockIdx.x;
    const int j0 = threadIdx.x;
    float acc0 = 0.f, acc1 = 0.f, acc2 = 0.f;
    for (int m = 0; m < MSA; m++) {
        const int* mrow = mask + m * SEQ;
        const float mi = (mrow[i] != 0) ? 1.0f : 0.0f;
        acc0 += mi * ((mrow[j0]       != 0) ? 1.0f : 0.0f);
        acc1 += mi * ((mrow[j0 + 128] != 0) ? 1.0f : 0.0f);
        acc2 += mi * ((mrow[j0 + 256] != 0) ? 1.0f : 0.0f);
    }
    g_count[i * SEQ + j0]       = acc0;
    g_count[i * SEQ + j0 + 128] = acc1;
    g_count[i * SEQ + j0 + 256] = acc2;
}

// ---------------------------------------------------------------------------
// Kernel 3: transpose wo -> g_wo[p][cd], tf32-rounded
// ---------------------------------------------------------------------------
__global__ void wo_prep_kernel(const float* __restrict__ wo)
{
    const int p = blockIdx.x;
    for (int k = threadIdx.x; k < 1024; k += 256)
        g_wo[(size_t)p * 1024 + k] = tf32r(wo[(size_t)k * DP + p]);
}

// ---------------------------------------------------------------------------
// GEMM1 (mma.sync tf32, cp.async double-buffered, frag pipeline):
// outer = L' x R'^T.  M=N=12288, K=256. CTA 128x128, 4 warps, warp 64x64.
// Epilogue: tf32-round, direct float2 stores to g_outer (32B sectors).
// ---------------------------------------------------------------------------
__global__ void __launch_bounds__(128, 2)
gemm1_kernel()
{
    extern __shared__ __align__(16) char dsm[];
    const uint32_t s0 = smem_u32(dsm);

    const int tid  = threadIdx.x;
    const int wid  = tid >> 5;
    const int lane = tid & 31;
    const int warpM = wid & 1;
    const int warpN = wid >> 1;
    const int aRow0 = blockIdx.x * 128;
    const int bRow0 = blockIdx.y * 128;
    const int lj = tid & 7;             // 16B col group for loads
    const int lr = tid >> 3;            // 0..15

    const uint32_t aFragOff =
        (uint32_t)(((warpM * 64 + (lane & 15)) * SPADF + (lane >> 4) * 4) * 4);
    const uint32_t bFragOff =
        (uint32_t)(((warpN * 64 + (lane & 7) + ((lane >> 4) << 3)) * SPADF
                    + ((lane >> 3) & 1) * 4) * 4);

    float acc[4][8][4];
#pragma unroll
    for (int mt = 0; mt < 4; mt++)
#pragma unroll
        for (int nt = 0; nt < 8; nt++)
#pragma unroll
            for (int e = 0; e < 4; e++) acc[mt][nt][e] = 0.f;

    auto issue = [&](int kc) {
        const int st = kc & 1;
        const int k0 = kc * BKF;
        const uint32_t sa = s0 + st * STAGEB;
        const uint32_t sb = sa + ABYTES;
#pragma unroll
        for (int q = 0; q < 8; q++) {
            const int r = lr + q * 16;
            cp16(sa + (uint32_t)((r * SPADF + lj * 4) * 4),
                 &g_lf[(size_t)(aRow0 + r) * 256 + k0 + lj * 4]);
            cp16(sb + (uint32_t)((r * SPADF + lj * 4) * 4),
                 &g_rf[(size_t)(bRow0 + r) * 256 + k0 + lj * 4]);
        }
        cp_commit();
    };

    uint32_t af[2][4][4], bf_[2][4][4];

    issue(0);
    for (int kc = 0; kc < NK1; kc++) {
        if (kc + 1 < NK1) { issue(kc + 1); cp_wait1(); }
        else              { cp_wait0(); }
        __syncthreads();
        const int st = kc & 1;
        const uint32_t sa = s0 + st * STAGEB;
        const uint32_t sb = sa + ABYTES;

#pragma unroll
        for (int mt = 0; mt < 4; mt++)
            ldmat_x4(af[0][mt], sa + aFragOff + mt * (16 * SPADF * 4));
#pragma unroll
        for (int g = 0; g < 4; g++)
            ldmat_x4(bf_[0][g], sb + bFragOff + g * (16 * SPADF * 4));

#pragma unroll
        for (int ks = 0; ks < 4; ks++) {
            const int cur = ks & 1;
            if (ks < 3) {
                const uint32_t ko = (uint32_t)((ks + 1) * 32);   // 8 f32 = 32B
#pragma unroll
                for (int mt = 0; mt < 4; mt++)
                    ldmat_x4(af[cur ^ 1][mt], sa + aFragOff + mt * (16 * SPADF * 4) + ko);
#pragma unroll
                for (int g = 0; g < 4; g++)
                    ldmat_x4(bf_[cur ^ 1][g], sb + bFragOff + g * (16 * SPADF * 4) + ko);
            }
#pragma unroll
            for (int nt = 0; nt < 8; nt++) {
                const uint32_t b0 = bf_[cur][nt >> 1][(nt & 1) * 2];
                const uint32_t b1 = bf_[cur][nt >> 1][(nt & 1) * 2 + 1];
#pragma unroll
                for (int mt = 0; mt < 4; mt++)
                    mma_tf32(acc[mt][nt], af[cur][mt], b0, b1);
            }
        }
        __syncthreads();
    }

    // ---- epilogue: tf32-round, direct float2 stores (aligned 8B sectors) ----
    const int i0 = blockIdx.x * 4;
    const int j0 = blockIdx.y * 4;
#pragma unroll
    for (int mt = 0; mt < 4; mt++)
#pragma unroll
        for (int nt = 0; nt < 8; nt++)
#pragma unroll
            for (int h = 0; h < 2; h++) {
                const int rA = warpM * 64 + mt * 16 + (lane >> 2) + h * 8;
                const int cB = warpN * 64 + nt * 8 + (lane & 3) * 2;
                const int ii = rA >> 5, c = rA & 31;
                const int jj = cB >> 5, d = cB & 31;
                const size_t pair = (size_t)(i0 + ii) * SEQ + (j0 + jj);
                float2 v;
                v.x = tf32r(acc[mt][nt][h * 2 + 0]);
                v.y = tf32r(acc[mt][nt][h * 2 + 1]);
                *(float2*)&g_outer[pair * 1024 + c * 32 + d] = v;
            }
}

// ---------------------------------------------------------------------------
// GEMM2 (mma.sync tf32, cp.async double-buffered, frag pipeline):
// out = outer x wo^T.  M=147456, N=128, K=1024. Epilogue: +bo, /(count+eps).
// ---------------------------------------------------------------------------
__global__ void __launch_bounds__(128, 2)
gemm2_kernel(const float* __restrict__ bo, float* __restrict__ out)
{
    extern __shared__ __align__(16) char dsm[];
    const uint32_t s0 = smem_u32(dsm);

    const int tid  = threadIdx.x;
    const int wid  = tid >> 5;
    const int lane = tid & 31;
    const int warpM = wid & 1;
    const int warpN = wid >> 1;
    const size_t pair0 = (size_t)blockIdx.x * 128;
    const int lj = tid & 7;
    const int lr = tid >> 3;

    const uint32_t aFragOff =
        (uint32_t)(((warpM * 64 + (lane & 15)) * SPADF + (lane >> 4) * 4) * 4);
    const uint32_t bFragOff =
        (uint32_t)(((warpN * 64 + (lane & 7) + ((lane >> 4) << 3)) * SPADF
                    + ((lane >> 3) & 1) * 4) * 4);

    float acc[4][8][4];
#pragma unroll
    for (int mt = 0; mt < 4; mt++)
#pragma unroll
        for (int nt = 0; nt < 8; nt++)
#pragma unroll
            for (int e = 0; e < 4; e++) acc[mt][nt][e] = 0.f;

    auto issue = [&](int kc) {
        const int st = kc & 1;
        const int k0 = kc * BKF;
        const uint32_t sa = s0 + st * STAGEB;
        const uint32_t sb = sa + ABYTES;
#pragma unroll
        for (int q = 0; q < 8; q++) {
            const int r = lr + q * 16;
            cp16(sa + (uint32_t)((r * SPADF + lj * 4) * 4),
                 &g_outer[(pair0 + r) * 1024 + k0 + lj * 4]);
            cp16(sb + (uint32_t)((r * SPADF + lj * 4) * 4),
                 &g_wo[(size_t)r * 1024 + k0 + lj * 4]);
        }
        cp_commit();
    };

    uint32_t af[2][4][4], bf_[2][4][4];

    issue(0);
    for (int kc = 0; kc < NK2; kc++) {
        if (kc + 1 < NK2) { issue(kc + 1); cp_wait1(); }
        else              { cp_wait0(); }
        __syncthreads();
        const int st = kc & 1;
        const uint32_t sa = s0 + st * STAGEB;
        const uint32_t sb = sa + ABYTES;

#pragma unroll
        for (int mt = 0; mt < 4; mt++)
            ldmat_x4(af[0][mt], sa + aFragOff + mt * (16 * SPADF * 4));
#pragma unroll
        for (int g = 0; g < 4; g++)
            ldmat_x4(bf_[0][g], sb + bFragOff + g * (16 * SPADF * 4));

#pragma unroll
        for (int ks = 0; ks < 4; ks++) {
            const int cur = ks & 1;
            if (ks < 3) {
                const uint32_t ko = (uint32_t)((ks + 1) * 32);
#pragma unroll
                for (int mt = 0; mt < 4; mt++)
                    ldmat_x4(af[cur ^ 1][mt], sa + aFragOff + mt * (16 * SPADF * 4) + ko);
#pragma unroll
                for (int g = 0; g < 4; g++)
                    ldmat_x4(bf_[cur ^ 1][g], sb + bFragOff + g * (16 * SPADF * 4) + ko);
            }
#pragma unroll
            for (int nt = 0; nt < 8; nt++) {
                const uint32_t b0 = bf_[cur][nt >> 1][(nt & 1) * 2];
                const uint32_t b1 = bf_[cur][nt >> 1][(nt & 1) * 2 + 1];
#pragma unroll
                for (int mt = 0; mt < 4; mt++)
                    mma_tf32(acc[mt][nt], af[cur][mt], b0, b1);
            }
        }
        __syncthreads();
    }

    // Epilogue: (acc + bo[p]) / (count[pair] + eps)
#pragma unroll
    for (int mt = 0; mt < 4; mt++) {
#pragma unroll
        for (int h = 0; h < 2; h++) {
            const int rA = warpM * 64 + mt * 16 + (lane >> 2) + h * 8;
            const size_t pair = pair0 + rA;
            const float inv = 1.0f / (g_count[pair] + EPSV);
#pragma unroll
            for (int nt = 0; nt < 8; nt++) {
                const int p = warpN * 64 + nt * 8 + (lane & 3) * 2;
                float2 o;
                o.x = (acc[mt][nt][h * 2 + 0] + bo[p])     * inv;
                o.y = (acc[mt][nt][h * 2 + 1] + bo[p + 1]) * inv;
                *(float2*)&out[pair * DP + p] = o;
            }
        }
    }
}

// ---------------------------------------------------------------------------
extern "C" void kernel_launch(void* const* d_in, const int* in_sizes, int n_in,
                              void* d_out, int out_size)
{
    const float* x    = (const float*)d_in[0];
    const int*   mk   = (const int*)d_in[1];
    const float* ln_g = (const float*)d_in[2];
    const float* ln_b = (const float*)d_in[3];
    const float* wl   = (const float*)d_in[4];
    const float* bl   = (const float*)d_in[5];
    const float* wr   = (const float*)d_in[6];
    const float* br   = (const float*)d_in[7];
    const float* wo   = (const float*)d_in[8];
    const float* bo   = (const float*)d_in[9];
    float* out        = (float*)d_out;

    cudaFuncSetAttribute(gemm1_kernel,
                         cudaFuncAttributeMaxDynamicSharedMemorySize, SMEMSZ);
    cudaFuncSetAttribute(gemm2_kernel,
                         cudaFuncAttributeMaxDynamicSharedMemorySize, SMEMSZ);

    ln_proj_kernel<<<SEQ * 8, 64>>>(x, mk, ln_g, ln_b, wl, bl, wr, br);
    count_kernel<<<SEQ, 128>>>(mk);
    wo_prep_kernel<<<DP, 256>>>(wo);
    gemm1_kernel<<<dim3(AROWS / 128, AROWS / 128), 128, SMEMSZ>>>();
    gemm2_kernel<<<PAIRS / 128, 128, SMEMSZ>>>(bo, out);
}